// round 15
// baseline (speedup 1.0000x reference)
#include <cuda_runtime.h>
#include <math.h>
#include <stdint.h>

#define BB 32
#define TT 200
#define EE 32
#define HH 128
#define VV 8000
#define MM (BB*TT)            // 6400
#define NT63 63               // 128-col B frag tiles
#define NT64 125              // 64-col gemm n-tiles (125*64 = 8000)
#define MT128 50              // 128-row gemm m-tiles (t-major: tile mt = t in [4mt,4mt+4))
#define NGEMM 349             // persistent gemm CTAs (32+63+349 = 444 = 148*3)
#define TOTTILES (MT128*NT64) // 6250

// Scratch (device globals)
__device__ float g_ux[MM*HH];              // [m][h], m = b*TT + t
__device__ float g_Afrag[100*8192];        // A fragments, t-major rows (m' = t*32+b), tf32
__device__ float g_Bfrag[NT63*16384];      // B fragments (128-col tiles), tf32
__device__ volatile unsigned g_ready[MT128];  // per-m-tile readiness (32 = ready)
__device__ volatile unsigned g_bdone;         // prepB tiles done (63 = ready)

// ---------------------------------------------------------------------------
__device__ __forceinline__ float to_tf32(float x) {
    unsigned u;
    asm("cvt.rna.tf32.f32 %0, %1;" : "=r"(u) : "f"(x));
    return __uint_as_float(u);
}
__device__ __forceinline__ float tanh_fast(float x) {
    float r;
    asm("tanh.approx.f32 %0, %1;" : "=f"(r) : "f"(x));
    return r;
}
__device__ __forceinline__ void mma8(float c[4], const float4& a, float bx, float by) {
    asm("mma.sync.aligned.m16n8k8.row.col.f32.tf32.tf32.f32 "
        "{%0,%1,%2,%3},{%4,%5,%6,%7},{%8,%9},{%0,%1,%2,%3};"
        : "+f"(c[0]), "+f"(c[1]), "+f"(c[2]), "+f"(c[3])
        : "r"(__float_as_uint(a.x)), "r"(__float_as_uint(a.y)),
          "r"(__float_as_uint(a.z)), "r"(__float_as_uint(a.w)),
          "r"(__float_as_uint(bx)), "r"(__float_as_uint(by)));
}
__device__ __forceinline__ void cpa16(uint32_t s, const void* g) {
    asm volatile("cp.async.ca.shared.global [%0], [%1], 16;" :: "r"(s), "l"(g));
}

// ---------------------------------------------------------------------------
__global__ void k_zero() {
    int t = threadIdx.x;
    if (t < MT128) g_ready[t] = 0u;
    if (t == MT128) g_bdone = 0u;
}

// ---------------------------------------------------------------------------
// ux[m][h] (m = b*TT+t)  [verified]
// ---------------------------------------------------------------------------
__global__ void k_ux(const float* __restrict__ x, const float* __restrict__ Uw,
                     const float* __restrict__ Ub, const float* __restrict__ Wb) {
    __shared__ float UwT[EE][HH];
    __shared__ float xs[32][EE];
    __shared__ float bias[HH];
    int tid = threadIdx.x;

    for (int f = tid; f < HH * EE / 4; f += 256) {
        int h = f / (EE / 4), c = f % (EE / 4);
        float4 u = ((const float4*)Uw)[f];
        UwT[c * 4 + 0][h] = u.x;
        UwT[c * 4 + 1][h] = u.y;
        UwT[c * 4 + 2][h] = u.z;
        UwT[c * 4 + 3][h] = u.w;
    }
    if (tid < HH) bias[tid] = Ub[tid] + Wb[tid];
    int m0 = blockIdx.x * 32;
    {
        int r = tid / 8, c = tid % 8;
        ((float4*)&xs[r][0])[c] = ((const float4*)x)[(size_t)(m0 + r) * (EE / 4) + c];
    }
    __syncthreads();
    int h = tid % HH;
    int half = tid / HH;
    #pragma unroll
    for (int rr = 0; rr < 16; rr++) {
        int r = half * 16 + rr;
        float acc = bias[h];
        const float4* xv = (const float4*)&xs[r][0];
        #pragma unroll
        for (int e4 = 0; e4 < EE / 4; e4++) {
            float4 xf = xv[e4];
            acc += UwT[e4 * 4 + 0][h] * xf.x;
            acc += UwT[e4 * 4 + 1][h] * xf.y;
            acc += UwT[e4 * 4 + 2][h] * xf.z;
            acc += UwT[e4 * 4 + 3][h] * xf.w;
        }
        g_ux[(size_t)(m0 + r) * HH + h] = acc;
    }
}

// ---------------------------------------------------------------------------
// Fused: bid 0..31 rnn (producer), 32..94 prepB (producer), 95..443 gemm.
// ---------------------------------------------------------------------------
__global__ void __launch_bounds__(256, 3)
k_fused(const float* __restrict__ Ww, const float* __restrict__ Vw,
        const float* __restrict__ Vb, float* __restrict__ out,
        float* __restrict__ out_hidden) {
    extern __shared__ float dynsm[];   // 8192 floats (32 KB)
    int tid = threadIdx.x;
    __builtin_assume(tid >= 0 && tid < 256);
    int bid = blockIdx.x;

    if (bid < BB) {
        // ================= RNN (R9-exact core; t-major A scatter) =========
        float* hb = dynsm;             // 2*128
        int j    = tid >> 1;
        int half = tid & 1;
        int b    = bid;

        float4 w[16];
        const float4* Ww4 = (const float4*)Ww;
        #pragma unroll
        for (int i = 0; i < 16; i++)
            w[i] = Ww4[(size_t)j * 32 + half * 16 + i];

        if (half == 0) hb[j] = 0.0f;
        __syncthreads();

        const float* uxb = g_ux + (size_t)b * TT * HH;
        int kg = j >> 3, kl = j & 7;
        int kcol = (kl & 3) * 4 + 2 * (kl >> 2);

        float uxr = uxb[j];
        int p = 0;
        float v = 0.0f;
        for (int t = 0; t < TT; t++) {
            const float4* h4 = (const float4*)(hb + p * HH) + half * 16;
            int tn = (t + 1 < TT) ? t + 1 : t;
            float uxn = uxb[tn * HH + j];

            float a = 0.f, b2 = 0.f, c = 0.f, d = 0.f;
            #pragma unroll
            for (int i = 0; i < 16; i++) {
                float4 hv = h4[i];
                a  += w[i].x * hv.x;
                b2 += w[i].y * hv.y;
                c  += w[i].z * hv.z;
                d  += w[i].w * hv.w;
            }
            float acc = (a + b2) + (c + d);
            acc += __shfl_xor_sync(0xFFFFFFFFu, acc, 1);
            v = tanh_fast(acc + uxr);
            uxr = uxn;
            if (half == 0) {
                hb[(1 - p) * HH + j] = v;
                int m  = t * BB + b;               // t-major row index
                int mt = m >> 6, mr = m & 63;
                int im = mr >> 4, r = mr & 15;
                int idx = mt * 8192 + (kg * 4 + im) * 128
                        + ((r & 7) << 4) + kcol + (r >> 3);
                g_Afrag[idx] = to_tf32(v);
            }
            if ((t & 3) == 3) {                    // release tile t>>2
                __threadfence();
                __syncthreads();
                if (tid == 0) atomicAdd((unsigned*)&g_ready[t >> 2], 1u);
            } else {
                __syncthreads();
            }
            p ^= 1;
        }
        if (half == 0) out_hidden[b * HH + j] = v;

    } else if (bid < BB + NT63) {
        // ================= prepB (verified formulas; 2 x 32KB rounds) =====
        float* Bs = dynsm;             // 8192 floats
        int nt = bid - BB;
        int n0 = nt * 128;
        #pragma unroll
        for (int r4 = 0; r4 < 2; r4++) {
            #pragma unroll
            for (int i = 0; i < 8; i++) {
                int f   = tid + i * 256;           // 0..2047 float4 this round
                int nn  = f >> 4;                  // 0..127 row
                int c4l = f & 15;                  // local float4-in-row
                int gn  = n0 + nn;
                float4 v = (gn < VV)
                    ? ((const float4*)Vw)[(size_t)gn * 32 + r4 * 16 + c4l]
                    : make_float4(0.f, 0.f, 0.f, 0.f);
                int ip  = nn >> 4;
                int reg = ((nn >> 3) & 1) * 2 + (c4l & 1);
                int base = ((c4l >> 1) * 8 + ip) * 128 + ((nn & 7) << 4) + reg;
                Bs[base + 0]  = to_tf32(v.x);
                Bs[base + 4]  = to_tf32(v.y);
                Bs[base + 8]  = to_tf32(v.z);
                Bs[base + 12] = to_tf32(v.w);
            }
            __syncthreads();
            float4* dst = (float4*)g_Bfrag + (size_t)nt * 4096 + r4 * 2048;
            #pragma unroll
            for (int i = 0; i < 8; i++)
                dst[tid + i * 256] = ((float4*)Bs)[tid + i * 256];
            __syncthreads();
        }
        __threadfence();
        __syncthreads();
        if (tid == 0) atomicAdd((unsigned*)&g_bdone, 1u);

    } else {
        // ================= persistent GEMM consumer (R12 body) ============
        float4* Bs4 = (float4*)dynsm;  // 2048 float4 (32 KB)
        uint32_t sB = (uint32_t)__cvta_generic_to_shared(Bs4);
        int warp = tid >> 5;
        int lane = tid & 31;
        int g = bid - (BB + NT63);

        if (tid == 0) { while (g_bdone < (unsigned)NT63) __nanosleep(128); }
        __syncthreads();

        int wm = warp >> 1;   // 0..3
        int wn = warp & 1;    // 0..1
        int last_mt = -1;

        for (int tau = g; tau < TOTTILES; tau += NGEMM) {
            int mt = tau / NT64, nt = tau % NT64;

            if (mt != last_mt) {
                if (tid == 0) { while (g_ready[mt] < 32u) __nanosleep(128); }
                __syncthreads();
                last_mt = mt;
            }

            // B: 4-ip slice of 128-col frag tile nt>>1  [verified]
            const float4* Bsrc = (const float4*)g_Bfrag + (size_t)(nt >> 1) * 4096
                               + (size_t)(nt & 1) * 128;
            #pragma unroll
            for (int i = 0; i < 8; i++) {
                int f = tid + i * 256;
                int kgi = f >> 7, ipl = (f >> 5) & 3, l = f & 31;
                cpa16(sB + f * 16, Bsrc + (kgi * 8 + ipl) * 32 + l);
            }
            asm volatile("cp.async.commit_group;");

            const float4* Aw = (const float4*)g_Afrag
                             + (size_t)(2 * mt + (wm >> 1)) * 2048
                             + ((wm & 1) * 2) * 32 + lane;

            float c[2][4][4];
            #pragma unroll
            for (int a = 0; a < 2; a++)
                #pragma unroll
                for (int b = 0; b < 4; b++)
                    #pragma unroll
                    for (int d = 0; d < 4; d++) c[a][b][d] = 0.0f;

            float4 a_cur[2], a_nxt[2];
            a_cur[0] = Aw[0];
            a_cur[1] = Aw[32];

            asm volatile("cp.async.wait_group 0;");
            __syncthreads();

            #pragma unroll
            for (int kgi = 0; kgi < 16; kgi++) {
                if (kgi < 15) {
                    a_nxt[0] = Aw[(kgi + 1) * 128];
                    a_nxt[1] = Aw[(kgi + 1) * 128 + 32];
                }
                float4 b0 = Bs4[(kgi * 4 + wn * 2 + 0) * 32 + lane];
                float4 b1 = Bs4[(kgi * 4 + wn * 2 + 1) * 32 + lane];
                #pragma unroll
                for (int im = 0; im < 2; im++) {
                    mma8(c[im][0], a_cur[im], b0.x, b0.y);
                    mma8(c[im][1], a_cur[im], b0.z, b0.w);
                    mma8(c[im][2], a_cur[im], b1.x, b1.y);
                    mma8(c[im][3], a_cur[im], b1.z, b1.w);
                }
                a_cur[0] = a_nxt[0];
                a_cur[1] = a_nxt[1];
            }

            // epilogue: t-major remap. warp covers t = mt*4 + wm, batches = row&31
            int tq = mt * 4 + wm;
            int n0 = nt * 64 + wn * 32;
            #pragma unroll
            for (int nt4 = 0; nt4 < 4; nt4++) {
                int col = n0 + nt4 * 8 + (lane & 3) * 2;
                float vbx = Vb[col], vby = Vb[col + 1];
                #pragma unroll
                for (int im = 0; im < 2; im++) {
                    int bb = im * 16 + (lane >> 2);          // batch 0..23
                    float2 o0 = make_float2(c[im][nt4][0] + vbx, c[im][nt4][1] + vby);
                    float2 o1 = make_float2(c[im][nt4][2] + vbx, c[im][nt4][3] + vby);
                    *(float2*)(out + ((size_t)bb * TT + tq) * VV + col) = o0;
                    *(float2*)(out + ((size_t)(bb + 8) * TT + tq) * VV + col) = o1;
                }
            }
            __syncthreads();   // protect Bs4 before next tile's cp.async
        }
    }
}

// ---------------------------------------------------------------------------
extern "C" void kernel_launch(void* const* d_in, const int* in_sizes, int n_in,
                              void* d_out, int out_size) {
    const float* x  = (const float*)d_in[0];
    const float* Ww = (const float*)d_in[1];
    const float* Wb = (const float*)d_in[2];
    const float* Uw = (const float*)d_in[3];
    const float* Ub = (const float*)d_in[4];
    const float* Vw = (const float*)d_in[5];
    const float* Vb = (const float*)d_in[6];
    float* out = (float*)d_out;

    cudaFuncSetAttribute(k_fused, cudaFuncAttributeMaxDynamicSharedMemorySize, 32768);

    k_zero<<<1, 64>>>();
    k_ux<<<MM / 32, 256>>>(x, Uw, Ub, Wb);
    k_fused<<<BB + NT63 + NGEMM, 256, 32768>>>(Ww, Vw, Vb, out,
                                               out + (size_t)MM * VV);
}